// round 14
// baseline (speedup 1.0000x reference)
#include <cuda_runtime.h>
#include <cuda_bf16.h>
#include <cstdint>
#include <cstddef>

#define B_    128
#define T_    512
#define IN_   64
#define H_    1024
#define OUT_  64
#define NCTA  128             // 4 b-groups x 32 h-groups

// ---- k_rnn smem (bytes) ----
#define WPITCH   2064         // 1024 bf16 + 16B pad
#define W_STREAM (32 * WPITCH)            // 66048
#define OFF_W    0
#define OFF_A    (2 * W_STREAM)           // 132096
#define APITCH   528                      // 256 bf16 + 16B pad
#define A_STREAM (32 * APITCH)            // 16896
#define A_BUF    (2 * A_STREAM)           // 33792 (hi+lo)
#define OFF_D    OFF_A                    // D reduce aliased on A buf0 (8 x 4224 = 33792)
#define D_KQ     4224                     // [32][33] f32 per kq
#define SMEM_RNN (OFF_A + 2 * A_BUF)      // 199680

// ---- k_prex smem ----
#define XPITCH     144
#define PX_XSTREAM (128 * XPITCH)
#define PX_W       (2 * PX_XSTREAM)
#define PX_WSTREAM (64 * XPITCH)
#define PX_BIAS    (PX_W + 2 * PX_WSTREAM)
#define SMEM_PX    (PX_BIAS + 256)

// ---- k_predm smem ----
#define PPITCH     272
#define PD_ASTREAM (128 * PPITCH)
#define PD_W       (2 * PD_ASTREAM)
#define PD_WSTREAM (64 * PPITCH)
#define PD_BIAS    (PD_W + 2 * PD_WSTREAM)
#define SMEM_PD    (PD_BIAS + 256)

// ---------------- static device scratch --------------------------------------
__device__ __nv_bfloat16 g_Xhi[T_][B_][IN_];
__device__ __nv_bfloat16 g_Xlo[T_][B_][IN_];
__device__ __nv_bfloat16 g_Rhi[B_][T_][H_];    // fr state entering step t
__device__ __nv_bfloat16 g_Rlo[B_][T_][H_];
__device__ float         g_pre[T_][B_][H_];    // x@Win^T + biases + noise
__device__ __nv_bfloat16 g_Wohi[OUT_][H_];
__device__ __nv_bfloat16 g_Wolo[OUT_][H_];
__device__ unsigned g_arrive[4];
__device__ unsigned g_epoch[4];

// ---------------- helpers -----------------------------------------------------
static __device__ __forceinline__ uint32_t smem_u32(const void* p) {
    uint32_t a;
    asm("{ .reg .u64 t; cvta.to.shared.u64 t, %1; cvt.u32.u64 %0, t; }"
        : "=r"(a) : "l"(p));
    return a;
}
static __device__ __forceinline__ void ldsm4(uint32_t& r0, uint32_t& r1,
                                             uint32_t& r2, uint32_t& r3,
                                             uint32_t addr) {
    asm volatile("ldmatrix.sync.aligned.m8n8.x4.shared.b16 {%0,%1,%2,%3}, [%4];"
                 : "=r"(r0), "=r"(r1), "=r"(r2), "=r"(r3) : "r"(addr));
}
static __device__ __forceinline__ void mma16816(float* d, const uint32_t* a,
                                                uint32_t b0, uint32_t b1) {
    asm volatile(
        "mma.sync.aligned.m16n8k16.row.col.f32.bf16.bf16.f32 "
        "{%0,%1,%2,%3}, {%4,%5,%6,%7}, {%8,%9}, {%0,%1,%2,%3};"
        : "+f"(d[0]), "+f"(d[1]), "+f"(d[2]), "+f"(d[3])
        : "r"(a[0]), "r"(a[1]), "r"(a[2]), "r"(a[3]), "r"(b0), "r"(b1));
}
static __device__ __forceinline__ unsigned ld_acq(const unsigned* p) {
    unsigned v;
    asm volatile("ld.acquire.gpu.global.u32 %0, [%1];" : "=r"(v) : "l"(p));
    return v;
}
static __device__ __forceinline__ void st_rel(unsigned* p, unsigned v) {
    asm volatile("st.release.gpu.global.u32 [%0], %1;" :: "l"(p), "r"(v) : "memory");
}
static __device__ __forceinline__ unsigned atom_add_rel(unsigned* p, unsigned v) {
    unsigned old;
    asm volatile("atom.add.release.gpu.global.u32 %0, [%1], %2;"
                 : "=r"(old) : "l"(p), "r"(v) : "memory");
    return old;
}
static __device__ __forceinline__ uint32_t bfpack(float x, float y) {
    uint32_t r;
    asm("cvt.rn.satfinite.bf16x2.f32 %0, %1, %2;" : "=r"(r) : "f"(y), "f"(x));
    return r;
}
static __device__ __forceinline__ float bftrunc(float x) {
    return __bfloat162float(__float2bfloat16(x));
}

// ============================================================================
// Prep: x splits, fr0 -> g_R[.][0], W_out splits, barrier reset
// ============================================================================
__global__ void k_prep(const float* __restrict__ inp,
                       const float* __restrict__ fr0,
                       const float* __restrict__ Woutw) {
    int i = blockIdx.x * 256 + threadIdx.x;
    {
        int k = i & 63, b = (i >> 6) & 127, t = i >> 13;
        float f = inp[((size_t)b * T_ + t) * IN_ + k];
        __nv_bfloat16 hi = __float2bfloat16(f);
        g_Xhi[t][b][k] = hi;
        g_Xlo[t][b][k] = __float2bfloat16(f - __bfloat162float(hi));
    }
    if (i < B_ * H_) {
        int b = i >> 10, k = i & 1023;
        float f = fr0[(size_t)b * H_ + k];
        __nv_bfloat16 hi = __float2bfloat16(f);
        g_Rhi[b][0][k] = hi;
        g_Rlo[b][0][k] = __float2bfloat16(f - __bfloat162float(hi));
    }
    if (i < OUT_ * H_) {
        int o = i >> 10, k = i & 1023;
        float w = Woutw[(size_t)o * H_ + k];
        __nv_bfloat16 hi = __float2bfloat16(w);
        g_Wohi[o][k] = hi;
        g_Wolo[o][k] = __float2bfloat16(w - __bfloat162float(hi));
    }
    if (i < 4) { g_arrive[i] = 0u; g_epoch[i] = 0u; }
}

// ============================================================================
// k_prex: g_pre = x@Win^T + b_in + b_rec + noise  (HMMA 3-term, verified R12/13)
// ============================================================================
__global__ void __launch_bounds__(256)
k_prex(const float* __restrict__ Winw, const float* __restrict__ Winb,
       const float* __restrict__ Wrecb, const float* __restrict__ noise)
{
    extern __shared__ char smem[];
    const uint32_t sm = smem_u32(smem);
    const int tid = threadIdx.x, lane = tid & 31, mq = tid >> 5;
    const int t  = blockIdx.x >> 4;
    const int h0 = (blockIdx.x & 15) * 64;

    #pragma unroll
    for (int it = 0; it < 8; ++it) {
        int u = tid + it * 256;
        int s = u >> 10, row = (u >> 3) & 127, q = u & 7;
        const __nv_bfloat16* src = s ? &g_Xlo[t][row][q * 8] : &g_Xhi[t][row][q * 8];
        *reinterpret_cast<uint4*>(smem + s * PX_XSTREAM + row * XPITCH + q * 16) =
            __ldg(reinterpret_cast<const uint4*>(src));
    }
    #pragma unroll
    for (int it = 0; it < 2; ++it) {
        int u = tid + it * 256;
        int row = u >> 3, q = u & 7;
        float4 f0 = __ldg(reinterpret_cast<const float4*>(
            Winw + (size_t)(h0 + row) * IN_ + q * 8));
        float4 f1 = __ldg(reinterpret_cast<const float4*>(
            Winw + (size_t)(h0 + row) * IN_ + q * 8 + 4));
        uint4 hi = make_uint4(bfpack(f0.x, f0.y), bfpack(f0.z, f0.w),
                              bfpack(f1.x, f1.y), bfpack(f1.z, f1.w));
        uint4 lo = make_uint4(bfpack(f0.x - bftrunc(f0.x), f0.y - bftrunc(f0.y)),
                              bfpack(f0.z - bftrunc(f0.z), f0.w - bftrunc(f0.w)),
                              bfpack(f1.x - bftrunc(f1.x), f1.y - bftrunc(f1.y)),
                              bfpack(f1.z - bftrunc(f1.z), f1.w - bftrunc(f1.w)));
        *reinterpret_cast<uint4*>(smem + PX_W + row * XPITCH + q * 16) = hi;
        *reinterpret_cast<uint4*>(smem + PX_W + PX_WSTREAM + row * XPITCH + q * 16) = lo;
    }
    if (tid < 64)
        *reinterpret_cast<float*>(smem + PX_BIAS + tid * 4) =
            Winb[h0 + tid] + Wrecb[h0 + tid];
    __syncthreads();

    const int grp = lane >> 3, lr = lane & 7;
    const uint32_t aOff = (uint32_t)(mq * 16 + (grp & 1) * 8 + lr) * XPITCH +
                          (uint32_t)((grp >> 1) * 8) * 2;
    const uint32_t wLane = (uint32_t)(lane & 7) * XPITCH + (uint32_t)(grp * 8) * 2;

    float acc[8][4];
    #pragma unroll
    for (int n = 0; n < 8; ++n)
        #pragma unroll
        for (int j = 0; j < 4; ++j) acc[n][j] = 0.0f;

    #pragma unroll
    for (int p = 0; p < 2; ++p) {
        uint32_t ah0[4], al0[4], ah1[4], al1[4];
        ldsm4(ah0[0], ah0[1], ah0[2], ah0[3], sm + aOff + (p * 32) * 2);
        ldsm4(al0[0], al0[1], al0[2], al0[3], sm + PX_XSTREAM + aOff + (p * 32) * 2);
        ldsm4(ah1[0], ah1[1], ah1[2], ah1[3], sm + aOff + (p * 32 + 16) * 2);
        ldsm4(al1[0], al1[1], al1[2], al1[3], sm + PX_XSTREAM + aOff + (p * 32 + 16) * 2);
        #pragma unroll
        for (int nt = 0; nt < 8; ++nt) {
            uint32_t wh[4], wl[4];
            uint32_t wb = sm + PX_W + (uint32_t)(nt * 8) * XPITCH + wLane + (p * 32) * 2;
            ldsm4(wh[0], wh[1], wh[2], wh[3], wb);
            ldsm4(wl[0], wl[1], wl[2], wl[3], wb + PX_WSTREAM);
            mma16816(acc[nt], ah0, wh[0], wh[1]);
            mma16816(acc[nt], al0, wh[0], wh[1]);
            mma16816(acc[nt], ah0, wl[0], wl[1]);
            mma16816(acc[nt], ah1, wh[2], wh[3]);
            mma16816(acc[nt], al1, wh[2], wh[3]);
            mma16816(acc[nt], ah1, wl[2], wl[3]);
        }
    }

    const int r1 = mq * 16 + (lane >> 2);
    const int cb = (lane & 3) * 2;
    const float* bias = reinterpret_cast<const float*>(smem + PX_BIAS);
    #pragma unroll
    for (int nt = 0; nt < 8; ++nt) {
        int h = h0 + nt * 8 + cb;
        float b0 = bias[nt * 8 + cb], b1 = bias[nt * 8 + cb + 1];
        float2 n1 = __ldg(reinterpret_cast<const float2*>(
            noise + ((size_t)t * B_ + r1) * H_ + h));
        float2 n2 = __ldg(reinterpret_cast<const float2*>(
            noise + ((size_t)t * B_ + r1 + 8) * H_ + h));
        *reinterpret_cast<float2*>(&g_pre[t][r1][h]) =
            make_float2(acc[nt][0] + n1.x + b0, acc[nt][1] + n1.y + b1);
        *reinterpret_cast<float2*>(&g_pre[t][r1 + 8][h]) =
            make_float2(acc[nt][2] + n2.x + b0, acc[nt][3] + n2.y + b1);
    }
}

// ============================================================================
// Persistent HMMA RNN: 128 CTAs = (bg, hg), 512 threads, warp = (mh, kq 0..7).
// K = 1024 in 4 chunks of 256; W fragments via ldsm4 spanning 32 k.
// ============================================================================
__global__ void __launch_bounds__(512, 1)
k_rnn(const float* __restrict__ Wrecw,
      const float* __restrict__ fr0,
      float* __restrict__ out_rates)
{
    extern __shared__ char smem[];
    const uint32_t sm = smem_u32(smem);
    const int tid  = threadIdx.x;
    const int wid  = tid >> 5;
    const int lane = tid & 31;
    const int bg   = blockIdx.x & 3;
    const int hg   = blockIdx.x >> 2;
    const int b0   = bg * 32;
    const int h0   = hg * 32;

    // ---- stage W_rec slice (hi/lo bf16) once ---------------------------------
    for (int i = tid; i < 32 * H_; i += 512) {
        int row = i >> 10, k = i & 1023;
        float w = Wrecw[(size_t)(h0 + row) * H_ + k];
        __nv_bfloat16 hi = __float2bfloat16(w);
        __nv_bfloat16 lo = __float2bfloat16(w - __bfloat162float(hi));
        *reinterpret_cast<__nv_bfloat16*>(smem + OFF_W + row * WPITCH + k * 2) = hi;
        *reinterpret_cast<__nv_bfloat16*>(smem + OFF_W + W_STREAM + row * WPITCH + k * 2) = lo;
    }

    // ---- epilogue role: thread owns (b0+em, h0+en..+1); fr in registers -----
    const int em = tid >> 4;             // 0..31
    const int en = (tid & 15) * 2;       // 0,2,..,30
    const int eb = b0 + em;
    float frloc[2];
    {
        float2 f = *reinterpret_cast<const float2*>(fr0 + (size_t)eb * H_ + h0 + en);
        frloc[0] = f.x; frloc[1] = f.y;
    }

    // ---- warp/lane geometry ------------------------------------------------
    const int mh = wid & 1;
    const int kq = wid >> 1;             // 0..7 (32 k per chunk)
    const int grp = lane >> 3, lr = lane & 7;
    const uint32_t aOffA = (uint32_t)(mh * 16 + (grp & 1) * 8 + lr) * APITCH +
                           (uint32_t)((grp >> 1) * 8) * 2;
    // W ldsm4 covering 32 k: lane groups 0-3 -> k sub-blocks 0,8,16,24
    const uint32_t wOff4 = (uint32_t)(lane & 7) * WPITCH +
                           (uint32_t)(grp * 8) * 2;

    // staging map: 2048 uint4 per chunk, 4 per thread
    int pfS[4], pfRow[4], pfQ[4];
    #pragma unroll
    for (int it = 0; it < 4; ++it) {
        int u = tid + it * 512;
        pfS[it] = u >> 10; pfRow[it] = (u >> 5) & 31; pfQ[it] = u & 31;
    }
    __syncthreads();

    for (int t = 0; t < T_; ++t) {
        // ---- prefetch pre_static + chunk0 -------------------------------------
        float2 pre2 = __ldg(reinterpret_cast<const float2*>(
            &g_pre[t][eb][h0 + en]));
        uint4 pf[4];
        #pragma unroll
        for (int it = 0; it < 4; ++it) {
            const __nv_bfloat16* base = pfS[it] ? &g_Rlo[0][0][0] : &g_Rhi[0][0][0];
            pf[it] = __ldcg(reinterpret_cast<const uint4*>(
                base + ((size_t)(b0 + pfRow[it]) * T_ + t) * H_ + pfQ[it] * 8));
        }
        #pragma unroll
        for (int it = 0; it < 4; ++it)
            *reinterpret_cast<uint4*>(smem + OFF_A + pfS[it] * A_STREAM +
                                      pfRow[it] * APITCH + pfQ[it] * 16) = pf[it];
        #pragma unroll
        for (int it = 0; it < 4; ++it) {
            const __nv_bfloat16* base = pfS[it] ? &g_Rlo[0][0][0] : &g_Rhi[0][0][0];
            pf[it] = __ldcg(reinterpret_cast<const uint4*>(
                base + ((size_t)(b0 + pfRow[it]) * T_ + t) * H_ + 256 + pfQ[it] * 8));
        }
        __syncthreads();   // buf0 visible

        float acc[4][4];
        #pragma unroll
        for (int n = 0; n < 4; ++n)
            #pragma unroll
            for (int j = 0; j < 4; ++j) acc[n][j] = 0.0f;

        // ---- 4 chunks of 256k, double buffered ---------------------------------
        #pragma unroll
        for (int c = 0; c < 4; ++c) {
            {
                const uint32_t aHiB = sm + OFF_A + (c & 1) * A_BUF + aOffA;
                const uint32_t aLoB = aHiB + A_STREAM;
                const int klocal = kq * 32;
                uint32_t ah0[4], al0[4], ah1[4], al1[4];
                ldsm4(ah0[0], ah0[1], ah0[2], ah0[3], aHiB + klocal * 2);
                ldsm4(al0[0], al0[1], al0[2], al0[3], aLoB + klocal * 2);
                ldsm4(ah1[0], ah1[1], ah1[2], ah1[3], aHiB + (klocal + 16) * 2);
                ldsm4(al1[0], al1[1], al1[2], al1[3], aLoB + (klocal + 16) * 2);
                const uint32_t wB = sm + OFF_W + wOff4 + (c * 256 + klocal) * 2;
                #pragma unroll
                for (int n = 0; n < 4; ++n) {
                    uint32_t wh[4], wl[4];
                    ldsm4(wh[0], wh[1], wh[2], wh[3], wB + n * (8 * WPITCH));
                    ldsm4(wl[0], wl[1], wl[2], wl[3], wB + W_STREAM + n * (8 * WPITCH));
                    mma16816(acc[n], ah0, wh[0], wh[1]);
                    mma16816(acc[n], al0, wh[0], wh[1]);
                    mma16816(acc[n], ah0, wl[0], wl[1]);
                    mma16816(acc[n], ah1, wh[2], wh[3]);
                    mma16816(acc[n], al1, wh[2], wh[3]);
                    mma16816(acc[n], ah1, wl[2], wl[3]);
                }
            }
            if (c < 3) {
                const int nb = (c + 1) & 1;
                #pragma unroll
                for (int it = 0; it < 4; ++it)
                    *reinterpret_cast<uint4*>(smem + OFF_A + nb * A_BUF +
                                              pfS[it] * A_STREAM +
                                              pfRow[it] * APITCH + pfQ[it] * 16) = pf[it];
                if (c < 2) {
                    #pragma unroll
                    for (int it = 0; it < 4; ++it) {
                        const __nv_bfloat16* base =
                            pfS[it] ? &g_Rlo[0][0][0] : &g_Rhi[0][0][0];
                        pf[it] = __ldcg(reinterpret_cast<const uint4*>(
                            base + ((size_t)(b0 + pfRow[it]) * T_ + t) * H_ +
                            (c + 2) * 256 + pfQ[it] * 8));
                    }
                }
                __syncthreads();
            }
        }

        // ---- write partial D (aliased on A buf0; chunk3 read buf1) ------------
        {
            float* dq = reinterpret_cast<float*>(smem + OFF_D + kq * D_KQ);
            const int rr = mh * 16 + (lane >> 2);
            const int cc = (lane & 3) * 2;
            #pragma unroll
            for (int n = 0; n < 4; ++n) {
                dq[rr * 33 + n * 8 + cc]           = acc[n][0];
                dq[rr * 33 + n * 8 + cc + 1]       = acc[n][1];
                dq[(rr + 8) * 33 + n * 8 + cc]     = acc[n][2];
                dq[(rr + 8) * 33 + n * 8 + cc + 1] = acc[n][3];
            }
        }
        __syncthreads();

        // ---- epilogue: 8-way kq reduce + pre_static, tanh, leaky update --------
        {
            const float* dbase = reinterpret_cast<const float*>(smem + OFF_D);
            float s0 = 0.f, s1 = 0.f;
            #pragma unroll
            for (int q = 0; q < 8; ++q) {
                const float* src = dbase + q * (D_KQ / 4) + em * 33 + en;
                s0 += src[0]; s1 += src[1];
            }
            frloc[0] = 0.9f * frloc[0] + 0.1f * tanhf(s0 + pre2.x);
            frloc[1] = 0.9f * frloc[1] + 0.1f * tanhf(s1 + pre2.y);

            *reinterpret_cast<float2*>(
                out_rates + ((size_t)eb * T_ + t) * H_ + h0 + en) =
                make_float2(frloc[0], frloc[1]);

            if (t < T_ - 1) {
                size_t idx = ((size_t)eb * T_ + (t + 1)) * H_ + h0 + en;
                *reinterpret_cast<uint32_t*>(&g_Rhi[0][0][0] + idx) =
                    bfpack(frloc[0], frloc[1]);
                *reinterpret_cast<uint32_t*>(&g_Rlo[0][0][0] + idx) =
                    bfpack(frloc[0] - bftrunc(frloc[0]),
                           frloc[1] - bftrunc(frloc[1]));
            }
        }

        // ---- per-b-group grid barrier ------------------------------------------
        if (t < T_ - 1) {
            __syncthreads();
            if (tid == 0) {
                unsigned old = atom_add_rel(&g_arrive[bg], 1u);
                if (old == 32u * (unsigned)(t + 1) - 1u)
                    st_rel(&g_epoch[bg], (unsigned)(t + 1));
                else
                    while (ld_acq(&g_epoch[bg]) < (unsigned)(t + 1)) {}
            }
            __syncthreads();
        }
    }
}

// ============================================================================
// k_predm: preds = sigmoid(g_R[b][t] @ Wout^T + b)  (HMMA 3-term, verified)
// ============================================================================
__global__ void __launch_bounds__(256)
k_predm(const float* __restrict__ Woutb, float* __restrict__ preds)
{
    extern __shared__ char smem[];
    const uint32_t sm = smem_u32(smem);
    const int tid = threadIdx.x, lane = tid & 31, mq = tid >> 5;
    const int b  = blockIdx.x >> 2;
    const int t0 = (blockIdx.x & 3) * 128;

    if (tid < 64)
        *reinterpret_cast<float*>(smem + PD_BIAS + tid * 4) = Woutb[tid];

    const int grp = lane >> 3, lr = lane & 7;
    const uint32_t aOff = (uint32_t)(mq * 16 + (grp & 1) * 8 + lr) * PPITCH +
                          (uint32_t)((grp >> 1) * 8) * 2;
    const uint32_t wLane = (uint32_t)(lane & 7) * PPITCH + (uint32_t)(grp * 8) * 2;

    float acc[8][4];
    #pragma unroll
    for (int n = 0; n < 8; ++n)
        #pragma unroll
        for (int j = 0; j < 4; ++j) acc[n][j] = 0.0f;

    for (int c = 0; c < 8; ++c) {
        __syncthreads();
        #pragma unroll
        for (int it = 0; it < 16; ++it) {
            int u = tid + it * 256;
            int s = u >> 11, row = (u >> 4) & 127, q = u & 15;
            const __nv_bfloat16* base = s ? &g_Rlo[0][0][0] : &g_Rhi[0][0][0];
            *reinterpret_cast<uint4*>(smem + s * PD_ASTREAM + row * PPITCH + q * 16) =
                __ldg(reinterpret_cast<const uint4*>(
                    base + ((size_t)b * T_ + t0 + row) * H_ + c * 128 + q * 8));
        }
        #pragma unroll
        for (int it = 0; it < 8; ++it) {
            int u = tid + it * 256;
            int s = u >> 10, row = (u >> 4) & 63, q = u & 15;
            const __nv_bfloat16* base = s ? &g_Wolo[0][0] : &g_Wohi[0][0];
            *reinterpret_cast<uint4*>(smem + PD_W + s * PD_WSTREAM + row * PPITCH + q * 16) =
                __ldg(reinterpret_cast<const uint4*>(
                    base + (size_t)row * H_ + c * 128 + q * 8));
        }
        __syncthreads();

        #pragma unroll
        for (int p = 0; p < 4; ++p) {
            uint32_t ah0[4], al0[4], ah1[4], al1[4];
            ldsm4(ah0[0], ah0[1], ah0[2], ah0[3], sm + aOff + (p * 32) * 2);
            ldsm4(al0[0], al0[1], al0[2], al0[3], sm + PD_ASTREAM + aOff + (p * 32) * 2);
            ldsm4(ah1[0], ah1[1], ah1[2], ah1[3], sm + aOff + (p * 32 + 16) * 2);
            ldsm4(al1[0], al1[1], al1[2], al1[3], sm + PD_ASTREAM + aOff + (p * 32 + 16) * 2);
            #pragma unroll
            for (int nt = 0; nt < 8; ++nt) {
                uint32_t wh[4], wl[4];
                uint32_t wb = sm + PD_W + (uint32_t)(nt * 8) * PPITCH + wLane + (p * 32) * 2;
                ldsm4(wh[0], wh[1], wh[2], wh[3], wb);
                ldsm4(wl[0], wl[1], wl[2], wl[3], wb + PD_WSTREAM);
                mma16816(acc[nt], ah0, wh[0], wh[1]);
                mma16816(acc[nt], al0, wh[0], wh[1]);
                mma16816(acc[nt], ah0, wl[0], wl[1]);
                mma16816(acc[nt], ah1, wh[2], wh[3]);
                mma16816(acc[nt], al1, wh[2], wh[3]);
                mma16816(acc[nt], ah1, wl[2], wl[3]);
            }
        }
    }

    const int r1 = mq * 16 + (lane >> 2);
    const int cb = (lane & 3) * 2;
    const float* bias = reinterpret_cast<const float*>(smem + PD_BIAS);
    #pragma unroll
    for (int nt = 0; nt < 8; ++nt) {
        int col = nt * 8 + cb;
        float b0 = bias[col], b1 = bias[col + 1];
        float z0 = acc[nt][0] + b0, z1 = acc[nt][1] + b1;
        float z2 = acc[nt][2] + b0, z3 = acc[nt][3] + b1;
        *reinterpret_cast<float2*>(
            preds + ((size_t)b * T_ + t0 + r1) * OUT_ + col) =
            make_float2(1.0f / (1.0f + __expf(-z0)), 1.0f / (1.0f + __expf(-z1)));
        *reinterpret_cast<float2*>(
            preds + ((size_t)b * T_ + t0 + r1 + 8) * OUT_ + col) =
            make_float2(1.0f / (1.0f + __expf(-z2)), 1.0f / (1.0f + __expf(-z3)));
    }
}

// ============================================================================
extern "C" void kernel_launch(void* const* d_in, const int* in_sizes, int n_in,
                              void* d_out, int out_size) {
    (void)in_sizes; (void)n_in; (void)out_size;
    const float* inp   = (const float*)d_in[0];
    const float* fr0   = (const float*)d_in[1];
    const float* noise = (const float*)d_in[2];
    const float* Winw  = (const float*)d_in[3];
    const float* Winb  = (const float*)d_in[4];
    const float* Wrecw = (const float*)d_in[5];
    const float* Wrecb = (const float*)d_in[6];
    const float* Woutw = (const float*)d_in[7];
    const float* Woutb = (const float*)d_in[8];

    float* out   = (float*)d_out;
    float* preds = out;                                   // [B,T,OUT]
    float* rates = out + (size_t)B_ * T_ * OUT_;          // [B,T,H]

    static bool attr_set = false;
    if (!attr_set) {
        cudaFuncSetAttribute(k_prex, cudaFuncAttributeMaxDynamicSharedMemorySize, SMEM_PX);
        cudaFuncSetAttribute(k_rnn, cudaFuncAttributeMaxDynamicSharedMemorySize, SMEM_RNN);
        cudaFuncSetAttribute(k_predm, cudaFuncAttributeMaxDynamicSharedMemorySize, SMEM_PD);
        attr_set = true;
    }

    k_prep<<<(T_ * B_ * IN_) / 256, 256>>>(inp, fr0, Woutw);
    k_prex<<<T_ * 16, 256, SMEM_PX>>>(Winw, Winb, Wrecb, noise);
    k_rnn<<<NCTA, 512, SMEM_RNN>>>(Wrecw, fr0, rates);
    k_predm<<<(B_ * T_) / 128, 256, SMEM_PD>>>(Woutb, preds);
}

// round 15
// speedup vs baseline: 1.4753x; 1.4753x over previous
#include <cuda_runtime.h>
#include <cuda_bf16.h>
#include <cuda_fp16.h>
#include <cstdint>
#include <cstddef>

#define B_    128
#define T_    512
#define IN_   64
#define H_    1024
#define OUT_  64
#define NCTA  128             // 4 b-groups x 32 h-groups

// ---- k_rnn smem (bytes) ----
#define WPITCH   2064         // 1024 fp16 + 16B pad
#define OFF_W    0
#define OFF_A    (32 * WPITCH)            // 66048
#define APITCH   528                      // 256 fp16 + 16B pad
#define A_STREAM (32 * APITCH)            // 16896 (one buffer)
#define OFF_D    OFF_A                    // D reduce aliased on A buf0
#define D_KQ     4224                     // [32][33] f32 per kq
#define SMEM_RNN (OFF_A + 2 * A_STREAM)   // 99840

// ---- k_prex smem (bf16 3-term, unchanged/verified) ----
#define XPITCH     144
#define PX_XSTREAM (128 * XPITCH)
#define PX_W       (2 * PX_XSTREAM)
#define PX_WSTREAM (64 * XPITCH)
#define PX_BIAS    (PX_W + 2 * PX_WSTREAM)
#define SMEM_PX    (PX_BIAS + 256)

// ---- k_predm smem (fp16: A 1-term, W 2-term) ----
#define PPITCH     272        // 128 fp16 + 16B pad
#define PD_ASTREAM (128 * PPITCH)         // 34816 (single A stream)
#define PD_W       PD_ASTREAM             // W after A
#define PD_WSTREAM (64 * PPITCH)          // 17408
#define PD_BIAS    (PD_W + 2 * PD_WSTREAM)// 69632
#define SMEM_PD    (PD_BIAS + 256)        // 69888

// ---------------- static device scratch --------------------------------------
__device__ __nv_bfloat16 g_Xhi[T_][B_][IN_];   // x splits (k_prex, bf16)
__device__ __nv_bfloat16 g_Xlo[T_][B_][IN_];
__device__ __half        g_R[B_][T_][H_];      // fp16 fr state entering step t
__device__ float         g_pre[T_][B_][H_];    // x@Win^T + biases + noise
__device__ __half        g_Woh[OUT_][H_];      // W_out fp16 hi
__device__ __half        g_Wol[OUT_][H_];      // W_out fp16 residual
__device__ unsigned g_arrive[4];
__device__ unsigned g_epoch[4];

// ---------------- helpers -----------------------------------------------------
static __device__ __forceinline__ uint32_t smem_u32(const void* p) {
    uint32_t a;
    asm("{ .reg .u64 t; cvta.to.shared.u64 t, %1; cvt.u32.u64 %0, t; }"
        : "=r"(a) : "l"(p));
    return a;
}
static __device__ __forceinline__ void ldsm4(uint32_t& r0, uint32_t& r1,
                                             uint32_t& r2, uint32_t& r3,
                                             uint32_t addr) {
    asm volatile("ldmatrix.sync.aligned.m8n8.x4.shared.b16 {%0,%1,%2,%3}, [%4];"
                 : "=r"(r0), "=r"(r1), "=r"(r2), "=r"(r3) : "r"(addr));
}
static __device__ __forceinline__ void ldsm2(uint32_t& r0, uint32_t& r1,
                                             uint32_t addr) {
    asm volatile("ldmatrix.sync.aligned.m8n8.x2.shared.b16 {%0,%1}, [%2];"
                 : "=r"(r0), "=r"(r1) : "r"(addr));
}
// bf16 mma (k_prex)
static __device__ __forceinline__ void mma_bf16(float* d, const uint32_t* a,
                                                uint32_t b0, uint32_t b1) {
    asm volatile(
        "mma.sync.aligned.m16n8k16.row.col.f32.bf16.bf16.f32 "
        "{%0,%1,%2,%3}, {%4,%5,%6,%7}, {%8,%9}, {%0,%1,%2,%3};"
        : "+f"(d[0]), "+f"(d[1]), "+f"(d[2]), "+f"(d[3])
        : "r"(a[0]), "r"(a[1]), "r"(a[2]), "r"(a[3]), "r"(b0), "r"(b1));
}
// fp16 mma (k_rnn, k_predm)
static __device__ __forceinline__ void mma_f16(float* d, const uint32_t* a,
                                               uint32_t b0, uint32_t b1) {
    asm volatile(
        "mma.sync.aligned.m16n8k16.row.col.f32.f16.f16.f32 "
        "{%0,%1,%2,%3}, {%4,%5,%6,%7}, {%8,%9}, {%0,%1,%2,%3};"
        : "+f"(d[0]), "+f"(d[1]), "+f"(d[2]), "+f"(d[3])
        : "r"(a[0]), "r"(a[1]), "r"(a[2]), "r"(a[3]), "r"(b0), "r"(b1));
}
static __device__ __forceinline__ unsigned ld_acq(const unsigned* p) {
    unsigned v;
    asm volatile("ld.acquire.gpu.global.u32 %0, [%1];" : "=r"(v) : "l"(p));
    return v;
}
static __device__ __forceinline__ void st_rel(unsigned* p, unsigned v) {
    asm volatile("st.release.gpu.global.u32 [%0], %1;" :: "l"(p), "r"(v) : "memory");
}
static __device__ __forceinline__ unsigned atom_add_rel(unsigned* p, unsigned v) {
    unsigned old;
    asm volatile("atom.add.release.gpu.global.u32 %0, [%1], %2;"
                 : "=r"(old) : "l"(p), "r"(v) : "memory");
    return old;
}
static __device__ __forceinline__ uint32_t bfpack(float x, float y) {
    uint32_t r;
    asm("cvt.rn.satfinite.bf16x2.f32 %0, %1, %2;" : "=r"(r) : "f"(y), "f"(x));
    return r;
}
static __device__ __forceinline__ float bftrunc(float x) {
    return __bfloat162float(__float2bfloat16(x));
}
static __device__ __forceinline__ uint32_t h2pack(float x, float y) {
    __half2 h = __floats2half2_rn(x, y);
    return *reinterpret_cast<uint32_t*>(&h);
}

// ============================================================================
// Prep: x splits (bf16), fr0 -> g_R[.][0] (fp16), W_out fp16 2-term, barriers
// ============================================================================
__global__ void k_prep(const float* __restrict__ inp,
                       const float* __restrict__ fr0,
                       const float* __restrict__ Woutw) {
    int i = blockIdx.x * 256 + threadIdx.x;
    {
        int k = i & 63, b = (i >> 6) & 127, t = i >> 13;
        float f = inp[((size_t)b * T_ + t) * IN_ + k];
        __nv_bfloat16 hi = __float2bfloat16(f);
        g_Xhi[t][b][k] = hi;
        g_Xlo[t][b][k] = __float2bfloat16(f - __bfloat162float(hi));
    }
    if (i < B_ * H_) {
        int b = i >> 10, k = i & 1023;
        g_R[b][0][k] = __float2half(fr0[(size_t)b * H_ + k]);
    }
    if (i < OUT_ * H_) {
        int o = i >> 10, k = i & 1023;
        float w = Woutw[(size_t)o * H_ + k];
        __half hi = __float2half(w);
        g_Woh[o][k] = hi;
        g_Wol[o][k] = __float2half(w - __half2float(hi));
    }
    if (i < 4) { g_arrive[i] = 0u; g_epoch[i] = 0u; }
}

// ============================================================================
// k_prex: g_pre = x@Win^T + b_in + b_rec + noise  (bf16 HMMA 3-term, verified)
// ============================================================================
__global__ void __launch_bounds__(256)
k_prex(const float* __restrict__ Winw, const float* __restrict__ Winb,
       const float* __restrict__ Wrecb, const float* __restrict__ noise)
{
    extern __shared__ char smem[];
    const uint32_t sm = smem_u32(smem);
    const int tid = threadIdx.x, lane = tid & 31, mq = tid >> 5;
    const int t  = blockIdx.x >> 4;
    const int h0 = (blockIdx.x & 15) * 64;

    #pragma unroll
    for (int it = 0; it < 8; ++it) {
        int u = tid + it * 256;
        int s = u >> 10, row = (u >> 3) & 127, q = u & 7;
        const __nv_bfloat16* src = s ? &g_Xlo[t][row][q * 8] : &g_Xhi[t][row][q * 8];
        *reinterpret_cast<uint4*>(smem + s * PX_XSTREAM + row * XPITCH + q * 16) =
            __ldg(reinterpret_cast<const uint4*>(src));
    }
    #pragma unroll
    for (int it = 0; it < 2; ++it) {
        int u = tid + it * 256;
        int row = u >> 3, q = u & 7;
        float4 f0 = __ldg(reinterpret_cast<const float4*>(
            Winw + (size_t)(h0 + row) * IN_ + q * 8));
        float4 f1 = __ldg(reinterpret_cast<const float4*>(
            Winw + (size_t)(h0 + row) * IN_ + q * 8 + 4));
        uint4 hi = make_uint4(bfpack(f0.x, f0.y), bfpack(f0.z, f0.w),
                              bfpack(f1.x, f1.y), bfpack(f1.z, f1.w));
        uint4 lo = make_uint4(bfpack(f0.x - bftrunc(f0.x), f0.y - bftrunc(f0.y)),
                              bfpack(f0.z - bftrunc(f0.z), f0.w - bftrunc(f0.w)),
                              bfpack(f1.x - bftrunc(f1.x), f1.y - bftrunc(f1.y)),
                              bfpack(f1.z - bftrunc(f1.z), f1.w - bftrunc(f1.w)));
        *reinterpret_cast<uint4*>(smem + PX_W + row * XPITCH + q * 16) = hi;
        *reinterpret_cast<uint4*>(smem + PX_W + PX_WSTREAM + row * XPITCH + q * 16) = lo;
    }
    if (tid < 64)
        *reinterpret_cast<float*>(smem + PX_BIAS + tid * 4) =
            Winb[h0 + tid] + Wrecb[h0 + tid];
    __syncthreads();

    const int grp = lane >> 3, lr = lane & 7;
    const uint32_t aOff = (uint32_t)(mq * 16 + (grp & 1) * 8 + lr) * XPITCH +
                          (uint32_t)((grp >> 1) * 8) * 2;
    const uint32_t wLane = (uint32_t)(lane & 7) * XPITCH + (uint32_t)(grp * 8) * 2;

    float acc[8][4];
    #pragma unroll
    for (int n = 0; n < 8; ++n)
        #pragma unroll
        for (int j = 0; j < 4; ++j) acc[n][j] = 0.0f;

    #pragma unroll
    for (int p = 0; p < 2; ++p) {
        uint32_t ah0[4], al0[4], ah1[4], al1[4];
        ldsm4(ah0[0], ah0[1], ah0[2], ah0[3], sm + aOff + (p * 32) * 2);
        ldsm4(al0[0], al0[1], al0[2], al0[3], sm + PX_XSTREAM + aOff + (p * 32) * 2);
        ldsm4(ah1[0], ah1[1], ah1[2], ah1[3], sm + aOff + (p * 32 + 16) * 2);
        ldsm4(al1[0], al1[1], al1[2], al1[3], sm + PX_XSTREAM + aOff + (p * 32 + 16) * 2);
        #pragma unroll
        for (int nt = 0; nt < 8; ++nt) {
            uint32_t wh[4], wl[4];
            uint32_t wb = sm + PX_W + (uint32_t)(nt * 8) * XPITCH + wLane + (p * 32) * 2;
            ldsm4(wh[0], wh[1], wh[2], wh[3], wb);
            ldsm4(wl[0], wl[1], wl[2], wl[3], wb + PX_WSTREAM);
            mma_bf16(acc[nt], ah0, wh[0], wh[1]);
            mma_bf16(acc[nt], al0, wh[0], wh[1]);
            mma_bf16(acc[nt], ah0, wl[0], wl[1]);
            mma_bf16(acc[nt], ah1, wh[2], wh[3]);
            mma_bf16(acc[nt], al1, wh[2], wh[3]);
            mma_bf16(acc[nt], ah1, wl[2], wl[3]);
        }
    }

    const int r1 = mq * 16 + (lane >> 2);
    const int cb = (lane & 3) * 2;
    const float* bias = reinterpret_cast<const float*>(smem + PX_BIAS);
    #pragma unroll
    for (int nt = 0; nt < 8; ++nt) {
        int h = h0 + nt * 8 + cb;
        float b0 = bias[nt * 8 + cb], b1 = bias[nt * 8 + cb + 1];
        float2 n1 = __ldg(reinterpret_cast<const float2*>(
            noise + ((size_t)t * B_ + r1) * H_ + h));
        float2 n2 = __ldg(reinterpret_cast<const float2*>(
            noise + ((size_t)t * B_ + r1 + 8) * H_ + h));
        *reinterpret_cast<float2*>(&g_pre[t][r1][h]) =
            make_float2(acc[nt][0] + n1.x + b0, acc[nt][1] + n1.y + b1);
        *reinterpret_cast<float2*>(&g_pre[t][r1 + 8][h]) =
            make_float2(acc[nt][2] + n2.x + b0, acc[nt][3] + n2.y + b1);
    }
}

// ============================================================================
// Persistent fp16 HMMA RNN: 128 CTAs = (bg, hg), 256 thr, warp = (mh, kq 0..3).
// Single-term fp16: 64 MMA/warp/step (was 192 with bf16 3-term).
// ============================================================================
__global__ void __launch_bounds__(256, 1)
k_rnn(const float* __restrict__ Wrecw,
      const float* __restrict__ fr0,
      float* __restrict__ out_rates)
{
    extern __shared__ char smem[];
    const uint32_t sm = smem_u32(smem);
    const int tid  = threadIdx.x;
    const int wid  = tid >> 5;
    const int lane = tid & 31;
    const int bg   = blockIdx.x & 3;
    const int hg   = blockIdx.x >> 2;
    const int b0   = bg * 32;
    const int h0   = hg * 32;

    // ---- stage W_rec slice (fp16) once ---------------------------------------
    for (int i = tid; i < 32 * H_; i += 256) {
        int row = i >> 10, k = i & 1023;
        *reinterpret_cast<__half*>(smem + OFF_W + row * WPITCH + k * 2) =
            __float2half(Wrecw[(size_t)(h0 + row) * H_ + k]);
    }

    // ---- epilogue role: thread owns (b0+em, h0+en..+3); fp32 fr in registers --
    const int em = tid >> 3;
    const int en = (tid & 7) * 4;
    const int eb = b0 + em;
    float frloc[4];
    {
        float4 f = *reinterpret_cast<const float4*>(fr0 + (size_t)eb * H_ + h0 + en);
        frloc[0] = f.x; frloc[1] = f.y; frloc[2] = f.z; frloc[3] = f.w;
    }

    // ---- warp/lane geometry (R13) ---------------------------------------------
    const int mh = wid & 1;
    const int kq = wid >> 1;             // 0..3 (64 k per chunk per warp)
    const int grp = lane >> 3, lr = lane & 7;
    const uint32_t aOffA = (uint32_t)(mh * 16 + (grp & 1) * 8 + lr) * APITCH +
                           (uint32_t)((grp >> 1) * 8) * 2;
    const uint32_t wOff  = (uint32_t)(lane & 7) * WPITCH +
                           (uint32_t)(((lane >> 3) & 1) * 8) * 2;

    // staging map: 1024 uint4 per chunk (fp16 single stream), 4 per thread
    int pfRow[4], pfQ[4];
    #pragma unroll
    for (int it = 0; it < 4; ++it) {
        int u = tid + it * 256;
        pfRow[it] = u >> 5; pfQ[it] = u & 31;
    }
    __syncthreads();

    for (int t = 0; t < T_; ++t) {
        // ---- prefetch pre_static + chunk0 -------------------------------------
        float4 pre4 = __ldg(reinterpret_cast<const float4*>(
            &g_pre[t][eb][h0 + en]));
        uint4 pf[4];
        #pragma unroll
        for (int it = 0; it < 4; ++it)
            pf[it] = __ldcg(reinterpret_cast<const uint4*>(
                &g_R[b0 + pfRow[it]][t][pfQ[it] * 8]));
        #pragma unroll
        for (int it = 0; it < 4; ++it)
            *reinterpret_cast<uint4*>(smem + OFF_A +
                                      pfRow[it] * APITCH + pfQ[it] * 16) = pf[it];
        #pragma unroll
        for (int it = 0; it < 4; ++it)
            pf[it] = __ldcg(reinterpret_cast<const uint4*>(
                &g_R[b0 + pfRow[it]][t][256 + pfQ[it] * 8]));
        __syncthreads();   // buf0 visible

        float acc[4][4];
        #pragma unroll
        for (int n = 0; n < 4; ++n)
            #pragma unroll
            for (int j = 0; j < 4; ++j) acc[n][j] = 0.0f;

        // ---- 4 chunks of 256k, double buffered ---------------------------------
        #pragma unroll
        for (int c = 0; c < 4; ++c) {
            {
                const uint32_t aB = sm + OFF_A + (c & 1) * A_STREAM + aOffA;
                #pragma unroll
                for (int s = 0; s < 4; ++s) {
                    const int klocal = kq * 64 + s * 16;
                    uint32_t ah[4];
                    ldsm4(ah[0], ah[1], ah[2], ah[3], aB + klocal * 2);
                    const uint32_t wB = sm + OFF_W + wOff + (c * 256 + klocal) * 2;
                    #pragma unroll
                    for (int n = 0; n < 4; ++n) {
                        uint32_t wh0, wh1;
                        ldsm2(wh0, wh1, wB + n * (8 * WPITCH));
                        mma_f16(acc[n], ah, wh0, wh1);
                    }
                }
            }
            if (c < 3) {
                const int nb = (c + 1) & 1;
                #pragma unroll
                for (int it = 0; it < 4; ++it)
                    *reinterpret_cast<uint4*>(smem + OFF_A + nb * A_STREAM +
                                              pfRow[it] * APITCH + pfQ[it] * 16) = pf[it];
                if (c < 2) {
                    #pragma unroll
                    for (int it = 0; it < 4; ++it)
                        pf[it] = __ldcg(reinterpret_cast<const uint4*>(
                            &g_R[b0 + pfRow[it]][t][(c + 2) * 256 + pfQ[it] * 8]));
                }
                __syncthreads();
            }
        }

        // ---- write partial D (aliased on A buf0; chunk3 read buf1) ------------
        {
            float* dq = reinterpret_cast<float*>(smem + OFF_D + kq * D_KQ);
            const int rr = mh * 16 + (lane >> 2);
            const int cc = (lane & 3) * 2;
            #pragma unroll
            for (int n = 0; n < 4; ++n) {
                dq[rr * 33 + n * 8 + cc]           = acc[n][0];
                dq[rr * 33 + n * 8 + cc + 1]       = acc[n][1];
                dq[(rr + 8) * 33 + n * 8 + cc]     = acc[n][2];
                dq[(rr + 8) * 33 + n * 8 + cc + 1] = acc[n][3];
            }
        }
        __syncthreads();

        // ---- epilogue: kq reduce + pre_static, tanh, leaky update --------------
        {
            const float* dbase = reinterpret_cast<const float*>(smem + OFF_D);
            float s[4] = {0.f, 0.f, 0.f, 0.f};
            #pragma unroll
            for (int q = 0; q < 4; ++q) {
                const float* src = dbase + q * (D_KQ / 4) + em * 33 + en;
                s[0] += src[0]; s[1] += src[1]; s[2] += src[2]; s[3] += src[3];
            }
            float pp[4] = {pre4.x, pre4.y, pre4.z, pre4.w};
            #pragma unroll
            for (int j = 0; j < 4; ++j)
                frloc[j] = 0.9f * frloc[j] + 0.1f * tanhf(s[j] + pp[j]);

            *reinterpret_cast<float4*>(
                out_rates + ((size_t)eb * T_ + t) * H_ + h0 + en) =
                make_float4(frloc[0], frloc[1], frloc[2], frloc[3]);

            if (t < T_ - 1) {
                uint2 w = make_uint2(h2pack(frloc[0], frloc[1]),
                                     h2pack(frloc[2], frloc[3]));
                *reinterpret_cast<uint2*>(&g_R[eb][t + 1][h0 + en]) = w;
            }
        }

        // ---- per-b-group grid barrier ------------------------------------------
        if (t < T_ - 1) {
            __syncthreads();
            if (tid == 0) {
                unsigned old = atom_add_rel(&g_arrive[bg], 1u);
                if (old == 32u * (unsigned)(t + 1) - 1u)
                    st_rel(&g_epoch[bg], (unsigned)(t + 1));
                else
                    while (ld_acq(&g_epoch[bg]) < (unsigned)(t + 1)) {}
            }
            __syncthreads();
        }
    }
}

// ============================================================================
// k_predm: preds = sigmoid(g_R[b][t] @ Wout^T + b)
// fp16: A single term, W 2-term (hi + residual) -> 4 MMA per (p,nt)
// ============================================================================
__global__ void __launch_bounds__(256)
k_predm(const float* __restrict__ Woutb, float* __restrict__ preds)
{
    extern __shared__ char smem[];
    const uint32_t sm = smem_u32(smem);
    const int tid = threadIdx.x, lane = tid & 31, mq = tid >> 5;
    const int b  = blockIdx.x >> 2;
    const int t0 = (blockIdx.x & 3) * 128;

    if (tid < 64)
        *reinterpret_cast<float*>(smem + PD_BIAS + tid * 4) = Woutb[tid];

    const int grp = lane >> 3, lr = lane & 7;
    const uint32_t aOff = (uint32_t)(mq * 16 + (grp & 1) * 8 + lr) * PPITCH +
                          (uint32_t)((grp >> 1) * 8) * 2;
    const uint32_t wLane = (uint32_t)(lane & 7) * PPITCH + (uint32_t)(grp * 8) * 2;

    float acc[8][4];
    #pragma unroll
    for (int n = 0; n < 8; ++n)
        #pragma unroll
        for (int j = 0; j < 4; ++j) acc[n][j] = 0.0f;

    for (int c = 0; c < 8; ++c) {
        __syncthreads();
        #pragma unroll
        for (int it = 0; it < 8; ++it) {             // A: 2048 uint4 (single)
            int u = tid + it * 256;
            int row = u >> 4, q = u & 15;
            *reinterpret_cast<uint4*>(smem + row * PPITCH + q * 16) =
                __ldg(reinterpret_cast<const uint4*>(
                    &g_R[b][t0 + row][c * 128 + q * 8]));
        }
        #pragma unroll
        for (int it = 0; it < 8; ++it) {             // W: 2048 uint4 (hi+lo)
            int u = tid + it * 256;
            int s = u >> 10, row = (u >> 4) & 63, q = u & 15;
            const __half* base = s ? &g_Wol[0][0] : &g_Woh[0][0];
            *reinterpret_cast<uint4*>(smem + PD_W + s * PD_WSTREAM + row * PPITCH + q * 16) =
                __ldg(reinterpret_cast<const uint4*>(
                    base + (size_t)row * H_ + c * 128 + q * 8));
        }
        __syncthreads();

        #pragma unroll
        for (int p = 0; p < 4; ++p) {
            uint32_t ah0[4], ah1[4];
            ldsm4(ah0[0], ah0[1], ah0[2], ah0[3], sm + aOff + (p * 32) * 2);
            ldsm4(ah1[0], ah1[1], ah1[2], ah1[3], sm + aOff + (p * 32 + 16) * 2);
            #pragma unroll
            for (int nt = 0; nt < 8; ++nt) {
                uint32_t wh[4], wl[4];
                uint32_t wb = sm + PD_W + (uint32_t)(nt * 8) * PPITCH + wLane + (p * 32) * 2;
                ldsm4(wh[0], wh[1], wh[2], wh[3], wb);
                ldsm4(wl[0], wl[1], wl[2], wl[3], wb + PD_WSTREAM);
                mma_f16(acc[nt], ah0, wh[0], wh[1]);
                mma_f16(acc[nt], ah0, wl[0], wl[1]);
                mma_f16(acc[nt], ah1, wh[2], wh[3]);
                mma_f16(acc[nt], ah1, wl[2], wl[3]);
            }
        }
    }

    const int r1 = mq * 16 + (lane >> 2);
    const int cb = (lane & 3) * 2;
    const float* bias = reinterpret_cast<const float*>(smem + PD_BIAS);
    #pragma unroll
    for (int nt = 0; nt < 8; ++nt) {
        int col = nt * 8 + cb;
        float b0 = bias[col], b1 = bias[col + 1];
        float z0 = acc[nt][0] + b0, z1 = acc[nt][1] + b1;
        float z2 = acc[nt][2] + b0, z3 = acc[nt][3] + b1;
        *reinterpret_cast<float2*>(
            preds + ((size_t)b * T_ + t0 + r1) * OUT_ + col) =
            make_float2(1.0f / (1.0f + __expf(-z0)), 1.0f / (1.0f + __expf(-z1)));
        *reinterpret_cast<float2*>(
            preds + ((size_t)b * T_ + t0 + r1 + 8) * OUT_ + col) =
            make_float2(1.0f / (1.0f + __expf(-z2)), 1.0f / (1.0f + __expf(-z3)));
    }
}

// ============================================================================
extern "C" void kernel_launch(void* const* d_in, const int* in_sizes, int n_in,
                              void* d_out, int out_size) {
    (void)in_sizes; (void)n_in; (void)out_size;
    const float* inp   = (const float*)d_in[0];
    const float* fr0   = (const float*)d_in[1];
    const float* noise = (const float*)d_in[2];
    const float* Winw  = (const float*)d_in[3];
    const float* Winb  = (const float*)d_in[4];
    const float* Wrecw = (const float*)d_in[5];
    const float* Wrecb = (const float*)d_in[6];
    const float* Woutw = (const float*)d_in[7];
    const float* Woutb = (const float*)d_in[8];

    float* out   = (float*)d_out;
    float* preds = out;                                   // [B,T,OUT]
    float* rates = out + (size_t)B_ * T_ * OUT_;          // [B,T,H]

    static bool attr_set = false;
    if (!attr_set) {
        cudaFuncSetAttribute(k_prex, cudaFuncAttributeMaxDynamicSharedMemorySize, SMEM_PX);
        cudaFuncSetAttribute(k_rnn, cudaFuncAttributeMaxDynamicSharedMemorySize, SMEM_RNN);
        cudaFuncSetAttribute(k_predm, cudaFuncAttributeMaxDynamicSharedMemorySize, SMEM_PD);
        attr_set = true;
    }

    k_prep<<<(T_ * B_ * IN_) / 256, 256>>>(inp, fr0, Woutw);
    k_prex<<<T_ * 16, 256, SMEM_PX>>>(Winw, Winb, Wrecb, noise);
    k_rnn<<<NCTA, 256, SMEM_RNN>>>(Wrecw, fr0, rates);
    k_predm<<<(B_ * T_) / 128, 256, SMEM_PD>>>(Woutb, preds);
}